// round 4
// baseline (speedup 1.0000x reference)
#include <cuda_runtime.h>
#include <math.h>
#include <stdint.h>

// Problem constants
#define B_   64
#define C_   512
#define HW_  784
#define NREG 64
#define TILE 28            // hw points per tile
#define NTILES (B_ * 28)   // 1792 tiles (28 tiles of 28 points per batch)

// ---------------- device scratch (static, allowed) ----------------
__device__ float g_scale[C_];
__device__ float g_shift[C_];
__device__ float g_a1[B_ * C_];          // l2-normalized t_feature rows
__device__ float g_att2[B_ * HW_];       // attention map 2
__device__ float g_score[B_ * NREG];
__device__ float g_pooled[B_ * C_];
__device__ float g_srea[(size_t)B_ * HW_ * NREG]; // layout [b*784+hw][n]
__device__ int   g_amax[B_];
__device__ float g_loss3;
__device__ float g_loss2acc;
__device__ float g_featn[B_ * C_];

// ---------------- f32x2 helpers ----------------
__device__ __forceinline__ void fma2(unsigned long long& acc,
                                     unsigned long long a,
                                     unsigned long long b) {
    asm("fma.rn.f32x2 %0, %1, %2, %0;" : "+l"(acc) : "l"(a), "l"(b));
}
__device__ __forceinline__ float2 unpk(unsigned long long v) {
    float2 f;
    asm("mov.b64 {%0, %1}, %2;" : "=f"(f.x), "=f"(f.y) : "l"(v));
    return f;
}

// ---------------- smem layout for k_main (floats) ----------------
// W rows padded to 516 floats: row n starts at bank (4n mod 32), so the 8
// distinct rows a warp loads per LDS.128 (n = wid*8 + r, r=0..7) hit banks
// {4r..4r+3} = all 32 banks -> 1 wavefront.
// X rows: 28 points x 516 floats, scalar layout; per LDS.128 a warp touches
// 4 distinct point-rows (banks 4p mod 32 distinct) -> 1 wavefront each.
#define OFF_W    0                      // 64 * 516  = 33024
#define OFF_X    33024                  // 28 * 516  = 14448
#define OFF_A1   (OFF_X + 14448)        // 512
#define OFF_SC   (OFF_A1 + 512)         // 512
#define OFF_SH   (OFF_SC + 512)         // 512
#define OFF_BI   (OFF_SH + 512)         // 64
#define OFF_ATT  (OFF_BI + 64)          // 28
#define OFF_PINV (OFF_ATT + 28)         // 28
#define OFF_NP   (OFF_PINV + 28)        // 8 warps * 28 points = 224
#define SMEM_FLOATS (OFF_NP + 224)
#define SMEM_BYTES  (SMEM_FLOATS * 4)   // 197408 B

// ---------------- init ----------------
__global__ void k_init() {
    int i = blockIdx.x * blockDim.x + threadIdx.x;
    int stride = gridDim.x * blockDim.x;
    const int tot = B_ * NREG + B_ * C_;
    for (int k = i; k < tot; k += stride) {
        if (k < B_ * NREG) g_score[k] = 0.f;
        else               g_pooled[k - B_ * NREG] = 0.f;
    }
    if (i == 0) { g_loss3 = 0.f; g_loss2acc = 0.f; }
}

// ---------------- BN statistics -> scale/shift ----------------
__global__ __launch_bounds__(256) void k_bn(const float* __restrict__ v,
                                            const float* __restrict__ gamma,
                                            const float* __restrict__ beta) {
    int c = blockIdx.x;
    int tid = threadIdx.x;
    float s = 0.f, s2 = 0.f;
    const float4* vp = (const float4*)v + (size_t)c * 196;
    for (int b = 0; b < B_; ++b) {
        const float4* r = vp + (size_t)b * C_ * 196;
        for (int i = tid; i < 196; i += 256) {
            float4 q = r[i];
            s  += (q.x + q.y) + (q.z + q.w);
            s2 += fmaf(q.x, q.x, q.y * q.y) + fmaf(q.z, q.z, q.w * q.w);
        }
    }
    __shared__ float rs[256], rs2[256];
    rs[tid] = s; rs2[tid] = s2;
    __syncthreads();
    for (int o = 128; o; o >>= 1) {
        if (tid < o) { rs[tid] += rs[tid + o]; rs2[tid] += rs2[tid + o]; }
        __syncthreads();
    }
    if (tid == 0) {
        const float N = 50176.f;
        float mu  = rs[0] / N;
        float var = rs2[0] / N - mu * mu;
        float sc  = gamma[c] * rsqrtf(var + 1e-5f);
        g_scale[c] = sc;
        g_shift[c] = beta[c] - mu * sc;
    }
}

// ---------------- l2-normalize t_feature rows ----------------
__global__ __launch_bounds__(128) void k_a1(const float* __restrict__ t) {
    int b = blockIdx.x, tid = threadIdx.x;
    float ss = 0.f;
    for (int c = tid; c < C_; c += 128) { float x = t[b * C_ + c]; ss = fmaf(x, x, ss); }
    for (int o = 16; o; o >>= 1) ss += __shfl_xor_sync(0xffffffffu, ss, o);
    __shared__ float r[4];
    if ((tid & 31) == 0) r[tid >> 5] = ss;
    __syncthreads();
    float tot = (r[0] + r[1]) + (r[2] + r[3]);
    float inv = 1.f / fmaxf(sqrtf(tot), 1e-12f);
    for (int c = tid; c < C_; c += 128) g_a1[b * C_ + c] = t[b * C_ + c] * inv;
}

// ---------------- fused main: BN + norms + conv GEMM + score parts ----------------
__global__ __launch_bounds__(256, 1) void k_main(const float* __restrict__ v,
                                                 const float* __restrict__ cw,
                                                 const float* __restrict__ cb) {
    extern __shared__ float sm[];
    float* Ws   = sm + OFF_W;
    float* Xs   = sm + OFF_X;
    float* A1s  = sm + OFF_A1;
    float* SCs  = sm + OFF_SC;
    float* SHs  = sm + OFF_SH;
    float* BIs  = sm + OFF_BI;
    float* ATTs = sm + OFF_ATT;
    float* PINV = sm + OFF_PINV;
    float* NPs  = sm + OFF_NP;

    const int tid  = threadIdx.x;
    const int lane = tid & 31;
    const int wid  = tid >> 5;
    // GEMM mapping: region n = wid*8 + r, point slice ps covers p = ps*7 + j
    const int r    = lane >> 2;
    const int ps   = lane & 3;
    const int n    = wid * 8 + r;

    // one-time preload: scale/shift, bias, W (padded rows of 516)
    for (int i = tid; i < C_; i += 256) { SCs[i] = g_scale[i]; SHs[i] = g_shift[i]; }
    if (tid < NREG) BIs[tid] = cb[tid];
    {
        const float4* w4p = (const float4*)cw;
        for (int i = tid; i < NREG * (C_ / 4); i += 256) {
            int nn = i >> 7, kq = i & 127;
            float4 q = w4p[i];
            float* d = &Ws[nn * 516 + kq * 4];
            d[0] = q.x; d[1] = q.y; d[2] = q.z; d[3] = q.w;
        }
    }

    const float* wr = &Ws[n * 516];
    const float* xr = &Xs[ps * 7 * 516];   // this slice's 7 point rows

    for (int tile = blockIdx.x; tile < NTILES; tile += gridDim.x) {
        int b   = tile / 28;
        int tt  = tile - b * 28;
        int hw0 = tt * TILE;

        __syncthreads();   // protect Xs/ATTs/A1s from previous iteration's readers

        // load a1 row for this b
        for (int i = tid; i < C_; i += 256) A1s[i] = g_a1[b * C_ + i];

        // load x tile with fused BN (float4 over hw; 28 = 7 float4)
        {
            const float4* vb = (const float4*)v + (size_t)b * C_ * 196 + tt * 7;
            for (int i = tid; i < C_ * 7; i += 256) {
                int c  = i / 7;
                int pq = i - c * 7;
                float4 q = vb[(size_t)c * 196 + pq];
                float sc = SCs[c], sh = SHs[c];
                float* d = &Xs[(pq * 4) * 516 + c];
                d[0 * 516] = fmaf(q.x, sc, sh);
                d[1 * 516] = fmaf(q.y, sc, sh);
                d[2 * 516] = fmaf(q.z, sc, sh);
                d[3 * 516] = fmaf(q.w, sc, sh);
            }
        }
        __syncthreads();

        // per-point: channel norm + att_map2 (8 warps over 28 points)
        for (int p = wid; p < TILE; p += 8) {
            const float* xp = &Xs[p * 516];
            float ss = 0.f, da = 0.f;
            for (int c = lane; c < C_; c += 32) {
                float xv = xp[c];
                ss = fmaf(xv, xv, ss);
                da = fmaf(xv, A1s[c], da);
            }
            for (int o = 16; o; o >>= 1) {
                ss += __shfl_xor_sync(0xffffffffu, ss, o);
                da += __shfl_xor_sync(0xffffffffu, da, o);
            }
            if (lane == 0) {
                float inv = 1.f / fmaxf(sqrtf(ss), 1e-12f);
                float av  = da * inv;
                ATTs[p] = av;
                g_att2[b * HW_ + hw0 + p] = av;
            }
        }

        // pooled accumulation (sum over the 28 points, atomic into global)
        for (int c = tid; c < C_; c += 256) {
            float s0 = 0.f, s1 = 0.f;
            #pragma unroll
            for (int p = 0; p < TILE; p += 2) {
                s0 += Xs[p * 516 + c];
                s1 += Xs[(p + 1) * 516 + c];
            }
            atomicAdd(&g_pooled[b * C_ + c], s0 + s1);
        }
        __syncthreads();   // ATTs ready

        // ---- GEMM: srea[p][n] = bias[n] + sum_c W[n][c]*x[p][c]
        //      f32x2 packed over CHANNEL pairs; thread = (region n, 7 points).
        unsigned long long a0 = 0ull, a1v = 0ull, a2v = 0ull, a3 = 0ull,
                           a4 = 0ull, a5 = 0ull, a6 = 0ull;
        #pragma unroll 4
        for (int k = 0; k < C_; k += 4) {
            ulonglong2 w = *(const ulonglong2*)(wr + k);   // (w0,w1),(w2,w3)
            ulonglong2 q;
            q = *(const ulonglong2*)(xr + 0 * 516 + k); fma2(a0,  q.x, w.x); fma2(a0,  q.y, w.y);
            q = *(const ulonglong2*)(xr + 1 * 516 + k); fma2(a1v, q.x, w.x); fma2(a1v, q.y, w.y);
            q = *(const ulonglong2*)(xr + 2 * 516 + k); fma2(a2v, q.x, w.x); fma2(a2v, q.y, w.y);
            q = *(const ulonglong2*)(xr + 3 * 516 + k); fma2(a3,  q.x, w.x); fma2(a3,  q.y, w.y);
            q = *(const ulonglong2*)(xr + 4 * 516 + k); fma2(a4,  q.x, w.x); fma2(a4,  q.y, w.y);
            q = *(const ulonglong2*)(xr + 5 * 516 + k); fma2(a5,  q.x, w.x); fma2(a5,  q.y, w.y);
            q = *(const ulonglong2*)(xr + 6 * 516 + k); fma2(a6,  q.x, w.x); fma2(a6,  q.y, w.y);
        }
        float bv = BIs[n];
        float s[7];
        { float2 f = unpk(a0);  s[0] = (f.x + f.y) + bv; }
        { float2 f = unpk(a1v); s[1] = (f.x + f.y) + bv; }
        { float2 f = unpk(a2v); s[2] = (f.x + f.y) + bv; }
        { float2 f = unpk(a3);  s[3] = (f.x + f.y) + bv; }
        { float2 f = unpk(a4);  s[4] = (f.x + f.y) + bv; }
        { float2 f = unpk(a5);  s[5] = (f.x + f.y) + bv; }
        { float2 f = unpk(a6);  s[6] = (f.x + f.y) + bv; }

        // region-norm per point: reduce s[j]^2 over the 8 regions of this
        // warp (xor over r: strides 4,8,16), then across warps via NPs.
        #pragma unroll
        for (int j = 0; j < 7; ++j) {
            float vsq = s[j] * s[j];
            vsq += __shfl_xor_sync(0xffffffffu, vsq, 4);
            vsq += __shfl_xor_sync(0xffffffffu, vsq, 8);
            vsq += __shfl_xor_sync(0xffffffffu, vsq, 16);
            if (r == 0) NPs[wid * 28 + ps * 7 + j] = vsq;
        }
        __syncthreads();
        if (tid < TILE) {
            float tot = 0.f;
            #pragma unroll
            for (int w8 = 0; w8 < 8; ++w8) tot += NPs[w8 * 28 + tid];
            PINV[tid] = 1.f / fmaxf(sqrtf(tot), 1e-12f);
        }
        __syncthreads();

        // write srea_n + per-region score partial
        float scl = 0.f;
        size_t obase = ((size_t)(b * HW_ + hw0 + ps * 7)) * NREG + n;
        #pragma unroll
        for (int j = 0; j < 7; ++j) {
            int p = ps * 7 + j;
            float sn = s[j] * PINV[p];
            g_srea[obase + (size_t)j * NREG] = sn;
            scl = fmaf(sn, ATTs[p], scl);
        }
        // reduce over the 4 point-slices (xor over ps: strides 1,2)
        scl += __shfl_xor_sync(0xffffffffu, scl, 1);
        scl += __shfl_xor_sync(0xffffffffu, scl, 2);
        if (ps == 0) atomicAdd(&g_score[b * NREG + n], scl);
    }
}

// ---------------- per-batch score statistics + loss3 ----------------
__global__ __launch_bounds__(64) void k_score() {
    int b = blockIdx.x, t = threadIdx.x;
    __shared__ float sv[NREG];
    sv[t] = g_score[b * NREG + t];
    __syncthreads();
    if (t == 0) {
        float sum = 0.f;
        for (int i = 0; i < NREG; ++i) sum += sv[i];
        float mean = sum / NREG;
        float sp = 0.f, sq = 0.f;
        int am = 0; float mx = sv[0];
        for (int i = 0; i < NREG; ++i) {
            if (sv[i] > mean) sp += sv[i]; else sq += sv[i];
            if (sv[i] > mx) { mx = sv[i]; am = i; }
        }
        sp *= (1.f / NREG); sq *= (1.f / NREG);
        float x = sq - sp;
        float spl = (x > 0.f) ? (x + log1pf(expf(-x))) : log1pf(expf(x));
        atomicAdd(&g_loss3, spl * (1.f / B_));
        g_amax[b] = am;
    }
}

// ---------------- JS divergence (loss2) ----------------
__global__ __launch_bounds__(256) void k_loss2() {
    int b = blockIdx.x, tid = threadIdx.x;
    __shared__ float P[HW_], Q[HW_];
    __shared__ float red[256];
    int am = g_amax[b];
    for (int i = tid; i < HW_; i += 256) {
        P[i] = g_att2[b * HW_ + i];
        Q[i] = g_srea[((size_t)(b * HW_ + i)) * NREG + am] * (1.f / NREG);
    }
    __syncthreads();

    float m = -3.0e38f;
    for (int i = tid; i < HW_; i += 256) m = fmaxf(m, P[i]);
    red[tid] = m; __syncthreads();
    for (int o = 128; o; o >>= 1) { if (tid < o) red[tid] = fmaxf(red[tid], red[tid + o]); __syncthreads(); }
    float mP = red[0]; __syncthreads();
    m = -3.0e38f;
    for (int i = tid; i < HW_; i += 256) m = fmaxf(m, Q[i]);
    red[tid] = m; __syncthreads();
    for (int o = 128; o; o >>= 1) { if (tid < o) red[tid] = fmaxf(red[tid], red[tid + o]); __syncthreads(); }
    float mQ = red[0]; __syncthreads();
    float sz = 0.f;
    for (int i = tid; i < HW_; i += 256) sz += expf(P[i] - mP);
    red[tid] = sz; __syncthreads();
    for (int o = 128; o; o >>= 1) { if (tid < o) red[tid] += red[tid + o]; __syncthreads(); }
    float lZP = logf(red[0]); __syncthreads();
    sz = 0.f;
    for (int i = tid; i < HW_; i += 256) sz += expf(Q[i] - mQ);
    red[tid] = sz; __syncthreads();
    for (int o = 128; o; o >>= 1) { if (tid < o) red[tid] += red[tid + o]; __syncthreads(); }
    float lZQ = logf(red[0]); __syncthreads();

    float kl = 0.f;
    for (int i = tid; i < HW_; i += 256) {
        float lp = P[i] - mP - lZP;
        float lq = Q[i] - mQ - lZQ;
        float p = expf(lp), q = expf(lq);
        float lm = logf(0.5f * (p + q));
        kl += p * (lp - lm) + q * (lq - lm);
    }
    red[tid] = kl; __syncthreads();
    for (int o = 128; o; o >>= 1) { if (tid < o) red[tid] += red[tid + o]; __syncthreads(); }
    if (tid == 0) atomicAdd(&g_loss2acc, red[0]);
}

// ---------------- feat = mean(mvsa) @ fc1^T + b, l2-normalized ----------------
__global__ __launch_bounds__(256) void k_feat(const float* __restrict__ fw,
                                              const float* __restrict__ fb) {
    int b = blockIdx.x, tid = threadIdx.x;
    int lane = tid & 31, wid = tid >> 5;
    __shared__ float pool[C_];
    __shared__ float ft[C_];
    __shared__ float red[256];
    for (int c = tid; c < C_; c += 256) pool[c] = g_pooled[b * C_ + c] * (1.f / HW_);
    __syncthreads();
    for (int o = wid; o < C_; o += 8) {
        const float* wrow = fw + (size_t)o * C_;
        float d = 0.f;
        for (int c = lane; c < C_; c += 32) d = fmaf(wrow[c], pool[c], d);
        for (int off = 16; off; off >>= 1) d += __shfl_xor_sync(0xffffffffu, d, off);
        if (lane == 0) ft[o] = d + fb[o];
    }
    __syncthreads();
    float ss = 0.f;
    for (int c = tid; c < C_; c += 256) { float x = ft[c]; ss = fmaf(x, x, ss); }
    red[tid] = ss; __syncthreads();
    for (int o = 128; o; o >>= 1) { if (tid < o) red[tid] += red[tid + o]; __syncthreads(); }
    float inv = 1.f / fmaxf(sqrtf(red[0]), 1e-12f);
    for (int c = tid; c < C_; c += 256) g_featn[b * C_ + c] = ft[c] * inv;
}

// ---------------- dual_sim = featn @ a1^T ----------------
__global__ __launch_bounds__(256) void k_dual(float* __restrict__ out) {
    int i = blockIdx.x, tid = threadIdx.x;
    int lane = tid & 31, wid = tid >> 5;
    __shared__ float fi[C_];
    for (int c = tid; c < C_; c += 256) fi[c] = g_featn[i * C_ + c];
    __syncthreads();
    for (int j = wid; j < B_; j += 8) {
        const float* ar = &g_a1[j * C_];
        float d = 0.f;
        for (int c = lane; c < C_; c += 32) d = fmaf(fi[c], ar[c], d);
        for (int off = 16; off; off >>= 1) d += __shfl_xor_sync(0xffffffffu, d, off);
        if (lane == 0) out[i * B_ + j] = d;
    }
}

// ---------------- final scalar ----------------
__global__ void k_final(float* __restrict__ out, int out_size) {
    if (out_size > B_ * B_) {
        float loss2 = 0.5f * g_loss2acc / B_;
        out[B_ * B_] = 0.1f * g_loss3 + 0.1f * loss2;
    }
}

// ---------------- launch ----------------
extern "C" void kernel_launch(void* const* d_in, const int* in_sizes, int n_in,
                              void* d_out, int out_size) {
    const float* v     = (const float*)d_in[0];   // [64,512,28,28]
    const float* t     = (const float*)d_in[1];   // [64,512]
    const float* cw    = (const float*)d_in[2];   // [64,512]
    const float* cb    = (const float*)d_in[3];   // [64]
    const float* gamma = (const float*)d_in[4];   // [512]
    const float* beta  = (const float*)d_in[5];   // [512]
    const float* fw    = (const float*)d_in[6];   // [512,512]
    const float* fb    = (const float*)d_in[7];   // [512]
    float* out = (float*)d_out;

    cudaFuncSetAttribute(k_main, cudaFuncAttributeMaxDynamicSharedMemorySize, SMEM_BYTES);

    k_init<<<64, 256>>>();
    k_bn<<<C_, 256>>>(v, gamma, beta);
    k_a1<<<B_, 128>>>(t);
    k_main<<<148, 256, SMEM_BYTES>>>(v, cw, cb);
    k_score<<<B_, 64>>>();
    k_loss2<<<B_, 256>>>();
    k_feat<<<B_, 256>>>(fw, fb);
    k_dual<<<B_, 256>>>(out);
    k_final<<<1, 1>>>(out, out_size);
}

// round 7
// speedup vs baseline: 2.0433x; 2.0433x over previous
#include <cuda_runtime.h>
#include <math.h>
#include <stdint.h>

// Problem constants
#define B_   64
#define C_   512
#define HW_  784
#define NREG 64
#define TILE 28            // hw points per tile
#define NTILES (B_ * 28)   // 1792 tiles (28 tiles of 28 points per batch)

// ---------------- device scratch (static, allowed) ----------------
__device__ float g_scale[C_];
__device__ float g_shift[C_];
__device__ float g_a1[B_ * C_];          // l2-normalized t_feature rows
__device__ float g_att2[B_ * HW_];       // attention map 2
__device__ float g_score[B_ * NREG];
__device__ float g_pooled[B_ * C_];
__device__ float g_srea[(size_t)B_ * HW_ * NREG]; // layout [b*784+hw][n]
__device__ float g_loss3;
__device__ float g_loss2acc;
__device__ float g_featn[B_ * C_];

// ---------------- f32x2 helpers ----------------
__device__ __forceinline__ void fma2(unsigned long long& acc,
                                     unsigned long long a,
                                     unsigned long long b) {
    asm("fma.rn.f32x2 %0, %1, %2, %0;" : "+l"(acc) : "l"(a), "l"(b));
}
__device__ __forceinline__ float2 unpk(unsigned long long v) {
    float2 f;
    asm("mov.b64 {%0, %1}, %2;" : "=f"(f.x), "=f"(f.y) : "l"(v));
    return f;
}

// ---------------- smem layout for k_main (floats) ----------------
// W rows padded to 516 floats: row n starts at bank (4n mod 32).
// GEMM lane mapping (pg = lane>>3, q = lane&7) with channel chunks
// k = q*4 + it*32: every 8-lane LDS.128 phase covers banks {4q..4q+3},
// i.e. all 32 banks -> 1 wavefront per phase (minimum possible).
// Stage buffer (channel-split combine) reuses Xs(+144 floats of A1s): 8
// wid-blocks of 1824 floats, inner addr q*228 + r*28 + pg*7 + j.
//   write banks: (228q + 7pg) mod 32 = (4q + 7pg): conflict-free (proof:
//     4dq == 7dpg mod 32 -> mod 4: 3dpg==0 -> dpg=0 -> dq=0).
//   read banks:  (28q + 7pg) mod 32: same argument mod 4.
// A1s spill is safe: A1s last read (norm phase) precedes stage write; A1s
// reload next tile follows the loop-top sync which follows stage reads.
#define OFF_W    0                      // 64 * 516  = 33024
#define OFF_X    33024                  // 28 * 516  = 14448 (stage: 14592)
#define OFF_A1   (OFF_X + 14448)        // 512
#define OFF_SC   (OFF_A1 + 512)         // 512
#define OFF_SH   (OFF_SC + 512)         // 512
#define OFF_BI   (OFF_SH + 512)         // 64
#define OFF_ATT  (OFF_BI + 64)          // 28
#define OFF_PINV (OFF_ATT + 28)         // 28
#define OFF_NP   (OFF_PINV + 28)        // 8 warps * 28 points = 224
#define SMEM_FLOATS (OFF_NP + 224)
#define SMEM_BYTES  (SMEM_FLOATS * 4)   // 197408 B

// ---------------- init ----------------
__global__ void k_init() {
    int i = blockIdx.x * blockDim.x + threadIdx.x;
    int stride = gridDim.x * blockDim.x;
    const int tot = B_ * NREG + B_ * C_;
    for (int k = i; k < tot; k += stride) {
        if (k < B_ * NREG) g_score[k] = 0.f;
        else               g_pooled[k - B_ * NREG] = 0.f;
    }
    if (i == 0) { g_loss3 = 0.f; g_loss2acc = 0.f; }
}

// ---------------- BN statistics -> scale/shift ----------------
__global__ __launch_bounds__(256) void k_bn(const float* __restrict__ v,
                                            const float* __restrict__ gamma,
                                            const float* __restrict__ beta) {
    int c = blockIdx.x;
    int tid = threadIdx.x;
    float s = 0.f, s2 = 0.f;
    const float4* vp = (const float4*)v + (size_t)c * 196;
    for (int b = 0; b < B_; ++b) {
        const float4* r = vp + (size_t)b * C_ * 196;
        for (int i = tid; i < 196; i += 256) {
            float4 q = r[i];
            s  += (q.x + q.y) + (q.z + q.w);
            s2 += fmaf(q.x, q.x, q.y * q.y) + fmaf(q.z, q.z, q.w * q.w);
        }
    }
    __shared__ float rs[256], rs2[256];
    rs[tid] = s; rs2[tid] = s2;
    __syncthreads();
    for (int o = 128; o; o >>= 1) {
        if (tid < o) { rs[tid] += rs[tid + o]; rs2[tid] += rs2[tid + o]; }
        __syncthreads();
    }
    if (tid == 0) {
        const float N = 50176.f;
        float mu  = rs[0] / N;
        float var = rs2[0] / N - mu * mu;
        float sc  = gamma[c] * rsqrtf(var + 1e-5f);
        g_scale[c] = sc;
        g_shift[c] = beta[c] - mu * sc;
    }
}

// ---------------- l2-normalize t_feature rows ----------------
__global__ __launch_bounds__(128) void k_a1(const float* __restrict__ t) {
    int b = blockIdx.x, tid = threadIdx.x;
    float ss = 0.f;
    for (int c = tid; c < C_; c += 128) { float x = t[b * C_ + c]; ss = fmaf(x, x, ss); }
    for (int o = 16; o; o >>= 1) ss += __shfl_xor_sync(0xffffffffu, ss, o);
    __shared__ float r[4];
    if ((tid & 31) == 0) r[tid >> 5] = ss;
    __syncthreads();
    float tot = (r[0] + r[1]) + (r[2] + r[3]);
    float inv = 1.f / fmaxf(sqrtf(tot), 1e-12f);
    for (int c = tid; c < C_; c += 128) g_a1[b * C_ + c] = t[b * C_ + c] * inv;
}

// ---------------- fused main: BN + norms + conv GEMM + score parts ----------------
__global__ __launch_bounds__(256, 1) void k_main(const float* __restrict__ v,
                                                 const float* __restrict__ cw,
                                                 const float* __restrict__ cb) {
    extern __shared__ float sm[];
    float* Ws   = sm + OFF_W;
    float* Xs   = sm + OFF_X;
    float* A1s  = sm + OFF_A1;
    float* SCs  = sm + OFF_SC;
    float* SHs  = sm + OFF_SH;
    float* BIs  = sm + OFF_BI;
    float* ATTs = sm + OFF_ATT;
    float* PINV = sm + OFF_PINV;
    float* NPs  = sm + OFF_NP;
    float* stage = Xs;                      // reused after GEMM each tile

    const int tid  = threadIdx.x;
    const int lane = tid & 31;
    const int wid  = tid >> 5;          // region group: n in [wid*8, wid*8+8)
    const int pg   = lane >> 3;         // point group:  p in [pg*7, pg*7+7)
    const int q    = lane & 7;          // channel slice / epilogue region select
    const int n    = wid * 8 + q;       // this thread's epilogue region

    // one-time preload: scale/shift, bias, W (padded rows of 516)
    for (int i = tid; i < C_; i += 256) { SCs[i] = g_scale[i]; SHs[i] = g_shift[i]; }
    if (tid < NREG) BIs[tid] = cb[tid];
    {
        const float4* w4p = (const float4*)cw;
        for (int i = tid; i < NREG * (C_ / 4); i += 256) {
            int nn = i >> 7, kq = i & 127;
            float4 qv = w4p[i];
            float* d = &Ws[nn * 516 + kq * 4];
            d[0] = qv.x; d[1] = qv.y; d[2] = qv.z; d[3] = qv.w;
        }
    }

    const float* wb = Ws + (wid * 8) * 516 + q * 4;
    const float* xb = Xs + (pg * 7) * 516 + q * 4;

    for (int tile = blockIdx.x; tile < NTILES; tile += gridDim.x) {
        int b   = tile / 28;
        int tt  = tile - b * 28;
        int hw0 = tt * TILE;

        __syncthreads();   // protect Xs/stage/ATTs/A1s from previous iteration's readers

        // load a1 row for this b
        for (int i = tid; i < C_; i += 256) A1s[i] = g_a1[b * C_ + i];

        // load x tile with fused BN (float4 over hw; 28 = 7 float4)
        {
            const float4* vb = (const float4*)v + (size_t)b * C_ * 196 + tt * 7;
            for (int i = tid; i < C_ * 7; i += 256) {
                int c  = i / 7;
                int pq = i - c * 7;
                float4 qv = vb[(size_t)c * 196 + pq];
                float sc = SCs[c], sh = SHs[c];
                float* d = &Xs[(pq * 4) * 516 + c];
                d[0 * 516] = fmaf(qv.x, sc, sh);
                d[1 * 516] = fmaf(qv.y, sc, sh);
                d[2 * 516] = fmaf(qv.z, sc, sh);
                d[3 * 516] = fmaf(qv.w, sc, sh);
            }
        }
        __syncthreads();

        // per-point: channel norm + att_map2 (8 warps over 28 points)
        for (int p = wid; p < TILE; p += 8) {
            const float* xp = &Xs[p * 516];
            float ss = 0.f, da = 0.f;
            for (int c = lane; c < C_; c += 32) {
                float xv = xp[c];
                ss = fmaf(xv, xv, ss);
                da = fmaf(xv, A1s[c], da);
            }
            for (int o = 16; o; o >>= 1) {
                ss += __shfl_xor_sync(0xffffffffu, ss, o);
                da += __shfl_xor_sync(0xffffffffu, da, o);
            }
            if (lane == 0) {
                float inv = 1.f / fmaxf(sqrtf(ss), 1e-12f);
                float av  = da * inv;
                ATTs[p] = av;
                g_att2[b * HW_ + hw0 + p] = av;
            }
        }

        // pooled accumulation (sum over the 28 points, atomic into global)
        for (int c = tid; c < C_; c += 256) {
            float s0 = 0.f, s1 = 0.f;
            #pragma unroll
            for (int p = 0; p < TILE; p += 2) {
                s0 += Xs[p * 516 + c];
                s1 += Xs[(p + 1) * 516 + c];
            }
            atomicAdd(&g_pooled[b * C_ + c], s0 + s1);
        }
        __syncthreads();   // ATTs ready; Xs fully built

        // ---- GEMM: 8 regions x 7 points per thread, 8-way channel split.
        //      acc[r][j] holds (even,odd) channel partial sums (f32x2).
        unsigned long long acc[56];
        #pragma unroll
        for (int i = 0; i < 56; ++i) acc[i] = 0ull;

        #pragma unroll 2
        for (int it = 0; it < 16; ++it) {
            const int k = it * 32;
            ulonglong2 w[8];
            #pragma unroll
            for (int r = 0; r < 8; ++r)
                w[r] = *(const ulonglong2*)(wb + r * 516 + k);
            #pragma unroll
            for (int j = 0; j < 7; ++j) {
                ulonglong2 x2 = *(const ulonglong2*)(xb + j * 516 + k);
                #pragma unroll
                for (int r = 0; r < 8; ++r) {
                    fma2(acc[r * 7 + j], x2.x, w[r].x);
                    fma2(acc[r * 7 + j], x2.y, w[r].y);
                }
            }
        }
        __syncthreads();   // all Xs reads done before stage overwrite

        // stage write: fold f32x2 halves, park per-(wid,q,r,pg,j)
        {
            float* st = stage + wid * 1824 + q * 228 + pg * 7;
            #pragma unroll
            for (int r = 0; r < 8; ++r) {
                #pragma unroll
                for (int j = 0; j < 7; ++j) {
                    float2 f = unpk(acc[r * 7 + j]);
                    st[r * 28 + j] = f.x + f.y;
                }
            }
        }
        __syncthreads();

        // fold over the 8 channel slices; thread takes region n = wid*8+q
        float sf[7];
        {
            const float* sr = stage + wid * 1824 + q * 28 + pg * 7;
            #pragma unroll
            for (int j = 0; j < 7; ++j) {
                float t0 = 0.f, t1 = 0.f;
                #pragma unroll
                for (int qq = 0; qq < 8; qq += 2) {
                    t0 += sr[qq * 228 + j];
                    t1 += sr[(qq + 1) * 228 + j];
                }
                sf[j] = (t0 + t1) + BIs[n];
            }
        }

        // region-norm partials: sum sf^2 over the 8 regions of this warp
        #pragma unroll
        for (int j = 0; j < 7; ++j) {
            float vv = sf[j] * sf[j];
            vv += __shfl_xor_sync(0xffffffffu, vv, 1);
            vv += __shfl_xor_sync(0xffffffffu, vv, 2);
            vv += __shfl_xor_sync(0xffffffffu, vv, 4);
            if (q == 0) NPs[wid * 28 + pg * 7 + j] = vv;
        }
        __syncthreads();
        if (tid < TILE) {
            float tot = 0.f;
            #pragma unroll
            for (int w8 = 0; w8 < 8; ++w8) tot += NPs[w8 * 28 + tid];
            PINV[tid] = 1.f / fmaxf(sqrtf(tot), 1e-12f);
        }
        __syncthreads();

        // write srea_n + per-region score partial
        float scl = 0.f;
        size_t obase = ((size_t)(b * HW_ + hw0 + pg * 7)) * NREG + n;
        #pragma unroll
        for (int j = 0; j < 7; ++j) {
            int p = pg * 7 + j;
            float sn = sf[j] * PINV[p];
            g_srea[obase + (size_t)j * NREG] = sn;
            scl = fmaf(sn, ATTs[p], scl);
        }
        // reduce over the 4 point groups (lane bits 3,4)
        scl += __shfl_xor_sync(0xffffffffu, scl, 8);
        scl += __shfl_xor_sync(0xffffffffu, scl, 16);
        if (pg == 0) atomicAdd(&g_score[b * NREG + n], scl);
    }
}

// ---------------- score stats + loss3 + JS divergence (loss2) ----------------
__global__ __launch_bounds__(256) void k_loss2() {
    int b = blockIdx.x, tid = threadIdx.x;
    __shared__ float P[HW_], Q[HW_];
    __shared__ float red[256];
    __shared__ float sv[NREG];
    __shared__ int s_am;

    if (tid < NREG) sv[tid] = g_score[b * NREG + tid];
    __syncthreads();
    if (tid == 0) {
        float sum = 0.f;
        for (int i = 0; i < NREG; ++i) sum += sv[i];
        float mean = sum / NREG;
        float sp = 0.f, sq = 0.f;
        int am = 0; float mx = sv[0];
        for (int i = 0; i < NREG; ++i) {
            if (sv[i] > mean) sp += sv[i]; else sq += sv[i];
            if (sv[i] > mx) { mx = sv[i]; am = i; }
        }
        sp *= (1.f / NREG); sq *= (1.f / NREG);
        float x = sq - sp;
        float spl = (x > 0.f) ? (x + log1pf(expf(-x))) : log1pf(expf(x));
        atomicAdd(&g_loss3, spl * (1.f / B_));
        s_am = am;
    }
    __syncthreads();
    int am = s_am;

    for (int i = tid; i < HW_; i += 256) {
        P[i] = g_att2[b * HW_ + i];
        Q[i] = g_srea[((size_t)(b * HW_ + i)) * NREG + am] * (1.f / NREG);
    }
    __syncthreads();

    float m = -3.0e38f;
    for (int i = tid; i < HW_; i += 256) m = fmaxf(m, P[i]);
    red[tid] = m; __syncthreads();
    for (int o = 128; o; o >>= 1) { if (tid < o) red[tid] = fmaxf(red[tid], red[tid + o]); __syncthreads(); }
    float mP = red[0]; __syncthreads();
    m = -3.0e38f;
    for (int i = tid; i < HW_; i += 256) m = fmaxf(m, Q[i]);
    red[tid] = m; __syncthreads();
    for (int o = 128; o; o >>= 1) { if (tid < o) red[tid] = fmaxf(red[tid], red[tid + o]); __syncthreads(); }
    float mQ = red[0]; __syncthreads();
    float sz = 0.f;
    for (int i = tid; i < HW_; i += 256) sz += expf(P[i] - mP);
    red[tid] = sz; __syncthreads();
    for (int o = 128; o; o >>= 1) { if (tid < o) red[tid] += red[tid + o]; __syncthreads(); }
    float lZP = logf(red[0]); __syncthreads();
    sz = 0.f;
    for (int i = tid; i < HW_; i += 256) sz += expf(Q[i] - mQ);
    red[tid] = sz; __syncthreads();
    for (int o = 128; o; o >>= 1) { if (tid < o) red[tid] += red[tid + o]; __syncthreads(); }
    float lZQ = logf(red[0]); __syncthreads();

    float kl = 0.f;
    for (int i = tid; i < HW_; i += 256) {
        float lp = P[i] - mP - lZP;
        float lq = Q[i] - mQ - lZQ;
        float p = expf(lp), qq = expf(lq);
        float lm = logf(0.5f * (p + qq));
        kl += p * (lp - lm) + qq * (lq - lm);
    }
    red[tid] = kl; __syncthreads();
    for (int o = 128; o; o >>= 1) { if (tid < o) red[tid] += red[tid + o]; __syncthreads(); }
    if (tid == 0) atomicAdd(&g_loss2acc, red[0]);
}

// ---------------- feat = mean(mvsa) @ fc1^T + b, l2-normalized ----------------
__global__ __launch_bounds__(256) void k_feat(const float* __restrict__ fw,
                                              const float* __restrict__ fb) {
    int b = blockIdx.x, tid = threadIdx.x;
    int lane = tid & 31, wid = tid >> 5;
    __shared__ float pool[C_];
    __shared__ float ft[C_];
    __shared__ float red[256];
    for (int c = tid; c < C_; c += 256) pool[c] = g_pooled[b * C_ + c] * (1.f / HW_);
    __syncthreads();
    for (int o = wid; o < C_; o += 8) {
        const float* wrow = fw + (size_t)o * C_;
        float d = 0.f;
        for (int c = lane; c < C_; c += 32) d = fmaf(wrow[c], pool[c], d);
        for (int off = 16; off; off >>= 1) d += __shfl_xor_sync(0xffffffffu, d, off);
        if (lane == 0) ft[o] = d + fb[o];
    }
    __syncthreads();
    float ss = 0.f;
    for (int c = tid; c < C_; c += 256) { float x = ft[c]; ss = fmaf(x, x, ss); }
    red[tid] = ss; __syncthreads();
    for (int o = 128; o; o >>= 1) { if (tid < o) red[tid] += red[tid + o]; __syncthreads(); }
    float inv = 1.f / fmaxf(sqrtf(red[0]), 1e-12f);
    for (int c = tid; c < C_; c += 256) g_featn[b * C_ + c] = ft[c] * inv;
}

// ---------------- dual_sim = featn @ a1^T (+ final scalar) ----------------
__global__ __launch_bounds__(256) void k_dual(float* __restrict__ out, int out_size) {
    int i = blockIdx.x, tid = threadIdx.x;
    int lane = tid & 31, wid = tid >> 5;
    __shared__ float fi[C_];
    for (int c = tid; c < C_; c += 256) fi[c] = g_featn[i * C_ + c];
    __syncthreads();
    for (int j = wid; j < B_; j += 8) {
        const float* ar = &g_a1[j * C_];
        float d = 0.f;
        for (int c = lane; c < C_; c += 32) d = fmaf(fi[c], ar[c], d);
        for (int off = 16; off; off >>= 1) d += __shfl_xor_sync(0xffffffffu, d, off);
        if (lane == 0) out[i * B_ + j] = d;
    }
    if (i == 0 && tid == 0 && out_size > B_ * B_) {
        float loss2 = 0.5f * g_loss2acc / B_;
        out[B_ * B_] = 0.1f * g_loss3 + 0.1f * loss2;
    }
}

// ---------------- launch ----------------
extern "C" void kernel_launch(void* const* d_in, const int* in_sizes, int n_in,
                              void* d_out, int out_size) {
    const float* v     = (const float*)d_in[0];   // [64,512,28,28]
    const float* t     = (const float*)d_in[1];   // [64,512]
    const float* cw    = (const float*)d_in[2];   // [64,512]
    const float* cb    = (const float*)d_in[3];   // [64]
    const float* gamma = (const float*)d_in[4];   // [512]
    const float* beta  = (const float*)d_in[5];   // [512]
    const float* fw    = (const float*)d_in[6];   // [512,512]
    const float* fb    = (const float*)d_in[7];   // [512]
    float* out = (float*)d_out;

    cudaFuncSetAttribute(k_main, cudaFuncAttributeMaxDynamicSharedMemorySize, SMEM_BYTES);

    k_init<<<64, 256>>>();
    k_bn<<<C_, 256>>>(v, gamma, beta);
    k_a1<<<B_, 128>>>(t);
    k_main<<<148, 256, SMEM_BYTES>>>(v, cw, cb);
    k_loss2<<<B_, 256>>>();
    k_feat<<<B_, 256>>>(fw, fb);
    k_dual<<<B_, 256>>>(out, out_size);
}